// round 2
// baseline (speedup 1.0000x reference)
#include <cuda_runtime.h>
#include <math.h>

#define TT   512
#define BB   64
#define HH   512
#define GG   2048   // 4*HH
#define EE   512
#define NCTA 128
#define UPC  4      // h-units per CTA  (HH / NCTA)
#define RPC  16     // gate rows per CTA (4 * UPC)

// ---------------- scratch (device globals; no runtime allocation) ----------------
__device__ float g_x0[(size_t)TT * EE * BB];   // embedded input,  [T][E][B]
__device__ float g_xw[(size_t)TT * GG * BB];   // xW + bias,       [T][G][B]
__device__ float g_y0[(size_t)TT * HH * BB];   // layer0 outputs,  [T][H][B]
__device__ float g_y1[(size_t)TT * HH * BB];   // layer1 outputs,  [T][H][B]
__device__ float g_hbuf[2 * HH * BB];          // double-buffered h, [2][H][B]
__device__ unsigned g_bar;                     // grid barrier counter (monotonic)

// ---------------- grid barrier (128 co-resident CTAs) ----------------
__device__ __forceinline__ void grid_sync() {
    __syncthreads();
    if (threadIdx.x == 0) {
        __threadfence();                                   // release my CTA's writes
        unsigned ticket = atomicAdd(&g_bar, 1u);
        unsigned target = ticket - (ticket & (NCTA - 1)) + NCTA;
        while (*(volatile unsigned*)&g_bar < target) { }
        __threadfence();                                   // acquire
    }
    __syncthreads();
}

// ---------------- embedding gather: g_x0[t][e][b] = emb[src[t][b]][e] ----------------
__global__ void embed_kernel(const int* __restrict__ src,
                             const float* __restrict__ emb) {
    size_t idx = (size_t)blockIdx.x * blockDim.x + threadIdx.x;
    if (idx >= (size_t)TT * EE * BB) return;
    int b = (int)(idx & 63);
    int e = (int)((idx >> 6) & (EE - 1));
    int t = (int)(idx >> 15);
    g_x0[idx] = emb[(size_t)src[t * BB + b] * EE + e];
}

// ---------------- GEMM: C[t][col][b] = sum_k A[t][k][b] * W[col][k] + bias[col] ----------------
// A: [T][512][64] (g_x0 or g_y0), W: [2048][512] row-major, C: g_xw [T][2048][64]
__global__ void __launch_bounds__(256) gemm_xw_kernel(const float* __restrict__ W,
                                                      const float* __restrict__ b1,
                                                      const float* __restrict__ b2,
                                                      int layer) {
    const float* __restrict__ A = layer ? g_y0 : g_x0;
    float* __restrict__ C = g_xw;

    __shared__ float As[16][64];    // [k][b]
    __shared__ float Ws[16][68];    // [k][col], padded

    const int tid = threadIdx.x;
    const int t   = blockIdx.y;
    const int n0  = blockIdx.x * 64;
    const int tx  = tid & 15;          // batch groups
    const int ty  = tid >> 4;          // col groups
    const int bb0 = tx * 4;
    const int cc0 = ty * 4;
    const int lw_n = tid >> 2;
    const int lw_k = (tid & 3) * 4;

    float acc[4][4];
    #pragma unroll
    for (int i = 0; i < 4; ++i)
        #pragma unroll
        for (int j = 0; j < 4; ++j) acc[i][j] = 0.f;

    for (int k0 = 0; k0 < 512; k0 += 16) {
        // A tile: direct copy (already [k][b])
        *(float4*)&As[ty][tx * 4] =
            *(const float4*)(A + ((size_t)t * 512 + k0 + ty) * 64 + tx * 4);
        // W tile: transpose into [k][col]
        float4 w = *(const float4*)(W + (size_t)(n0 + lw_n) * 512 + k0 + lw_k);
        Ws[lw_k + 0][lw_n] = w.x;
        Ws[lw_k + 1][lw_n] = w.y;
        Ws[lw_k + 2][lw_n] = w.z;
        Ws[lw_k + 3][lw_n] = w.w;
        __syncthreads();

        #pragma unroll
        for (int kk = 0; kk < 16; ++kk) {
            float4 a4 = *(const float4*)&As[kk][bb0];
            float4 w4 = *(const float4*)&Ws[kk][cc0];
            float av[4] = {a4.x, a4.y, a4.z, a4.w};
            float wv[4] = {w4.x, w4.y, w4.z, w4.w};
            #pragma unroll
            for (int i = 0; i < 4; ++i)
                #pragma unroll
                for (int j = 0; j < 4; ++j)
                    acc[i][j] = fmaf(av[i], wv[j], acc[i][j]);
        }
        __syncthreads();
    }

    #pragma unroll
    for (int j = 0; j < 4; ++j) {
        int col = n0 + cc0 + j;
        float bias = b1[col] + b2[col];
        float4 v;
        v.x = acc[0][j] + bias;
        v.y = acc[1][j] + bias;
        v.z = acc[2][j] + bias;
        v.w = acc[3][j] + bias;
        *(float4*)(C + ((size_t)t * GG + col) * BB + bb0) = v;
    }
}

// ---------------- persistent LSTM recurrence ----------------
// Each of 128 CTAs owns UPC=4 hidden units (16 gate rows). Per step:
//   stage full h into smem, gates = xw[t] + h @ Whh_slice^T, nonlinearity,
//   c update (smem-resident), write h to double buffer + layer output, grid barrier.
__global__ void __launch_bounds__(256, 1) lstm_rec_kernel(const float* __restrict__ Whh,
                                                          int layer) {
    extern __shared__ float smem[];
    float* sW = smem;                 // RPC * HH      =  8192
    float* sH = sW + RPC * HH;        // HH  * BB      = 32768
    float* sG = sH + HH * BB;         // RPC * BB      =  1024
    float* sC = sG + RPC * BB;        // UPC * BB      =   256

    const float* __restrict__ xw = g_xw;
    float* __restrict__ y = layer ? g_y1 : g_y0;
    float* hbuf = g_hbuf;

    const int tid = threadIdx.x;
    const int cta = blockIdx.x;
    const int u0  = cta * UPC;

    // Load Whh slice: local row r = q*4+j  <->  global row q*HH + u0 + j
    #pragma unroll
    for (int r = 0; r < RPC; ++r) {
        const int q = r >> 2, j = r & 3;
        const float* srcw = Whh + (size_t)(q * HH + u0 + j) * HH;
        for (int k = tid; k < HH; k += 256) sW[r * HH + k] = srcw[k];
    }
    for (int i = tid; i < UPC * BB; i += 256) sC[i] = 0.f;
    for (int i = tid; i < UPC * BB; i += 256) hbuf[u0 * BB + i] = 0.f;  // buffer 0
    grid_sync();

    // dot-phase mapping: thread = (r, bg): 16 gate rows x 16 batch-groups-of-4
    const int bg  = tid & 15;
    const int r   = tid >> 4;
    const int b0  = bg * 4;
    const int q   = r >> 2, j = r & 3;
    const int col = q * HH + u0 + j;
    // gate-phase mapping: thread = (jj, bb): 4 units x 64 batches
    const int bb = tid & 63, jj = tid >> 6;

    int cur = 0;
    for (int t = 0; t < TT; ++t) {
        // stage h[cur] (128 KB) into smem; __ldcg avoids stale L1 lines
        {
            const float4* hs = (const float4*)(hbuf + cur * HH * BB);
            float4* sh4 = (float4*)sH;
            #pragma unroll 4
            for (int i = tid; i < HH * BB / 4; i += 256) sh4[i] = __ldcg(hs + i);
        }
        __syncthreads();

        // gates[b0..b0+3][col] = xw[t][col][b0..] + sum_k h[b][k] * Whh[col][k]
        float4 acc = *(const float4*)(xw + ((size_t)t * GG + col) * BB + b0);
        const float4* wp = (const float4*)(sW + r * HH);
        #pragma unroll 4
        for (int k4 = 0; k4 < HH / 4; ++k4) {
            float4 w = wp[k4];
            const float* hp = sH + (k4 * 4) * BB + b0;
            float4 h0 = *(const float4*)(hp);
            float4 h1 = *(const float4*)(hp + BB);
            float4 h2 = *(const float4*)(hp + 2 * BB);
            float4 h3 = *(const float4*)(hp + 3 * BB);
            acc.x = fmaf(w.x, h0.x, fmaf(w.y, h1.x, fmaf(w.z, h2.x, fmaf(w.w, h3.x, acc.x))));
            acc.y = fmaf(w.x, h0.y, fmaf(w.y, h1.y, fmaf(w.z, h2.y, fmaf(w.w, h3.y, acc.y))));
            acc.z = fmaf(w.x, h0.z, fmaf(w.y, h1.z, fmaf(w.z, h2.z, fmaf(w.w, h3.z, acc.z))));
            acc.w = fmaf(w.x, h0.w, fmaf(w.y, h1.w, fmaf(w.z, h2.w, fmaf(w.w, h3.w, acc.w))));
        }
        *(float4*)(sG + r * BB + b0) = acc;
        __syncthreads();

        // gate nonlinearity + state update for unit (u0+jj), batch bb
        {
            float iv = sG[(0 * 4 + jj) * BB + bb];
            float fv = sG[(1 * 4 + jj) * BB + bb];
            float gv = sG[(2 * 4 + jj) * BB + bb];
            float ov = sG[(3 * 4 + jj) * BB + bb];
            iv = 1.f / (1.f + expf(-iv));
            fv = 1.f / (1.f + expf(-fv));
            gv = tanhf(gv);
            ov = 1.f / (1.f + expf(-ov));
            float c = fv * sC[jj * BB + bb] + iv * gv;
            sC[jj * BB + bb] = c;
            float h = ov * tanhf(c);
            hbuf[(cur ^ 1) * HH * BB + (u0 + jj) * BB + bb] = h;
            y[((size_t)t * HH + (u0 + jj)) * BB + bb] = h;
        }
        grid_sync();
        cur ^= 1;
    }
}

// ---------------- output gather: out[b][u] = y1[sen_len[b]-1][u][b] ----------------
__global__ void out_kernel(const int* __restrict__ sen_len, float* __restrict__ out) {
    int idx = blockIdx.x * blockDim.x + threadIdx.x;
    if (idx >= BB * HH) return;
    int b = idx >> 9;
    int u = idx & (HH - 1);
    int t = sen_len[b] - 1;
    out[idx] = g_y1[((size_t)t * HH + u) * BB + b];
}

// ---------------- launch ----------------
static const int REC_SMEM = (RPC * HH + HH * BB + RPC * BB + UPC * BB) * (int)sizeof(float); // 168960

extern "C" void kernel_launch(void* const* d_in, const int* in_sizes, int n_in,
                              void* d_out, int out_size) {
    const int*   src     = (const int*)d_in[0];
    const int*   sen_len = (const int*)d_in[1];
    const float* emb     = (const float*)d_in[2];
    const float* Wih0    = (const float*)d_in[3];
    const float* Whh0    = (const float*)d_in[4];
    const float* bih0    = (const float*)d_in[5];
    const float* bhh0    = (const float*)d_in[6];
    const float* Wih1    = (const float*)d_in[7];
    const float* Whh1    = (const float*)d_in[8];
    const float* bih1    = (const float*)d_in[9];
    const float* bhh1    = (const float*)d_in[10];
    float* out = (float*)d_out;

    cudaFuncSetAttribute(lstm_rec_kernel,
                         cudaFuncAttributeMaxDynamicSharedMemorySize, REC_SMEM);

    embed_kernel<<<(TT * EE * BB + 255) / 256, 256>>>(src, emb);

    dim3 ggrid(GG / 64, TT);
    gemm_xw_kernel<<<ggrid, 256>>>(Wih0, bih0, bhh0, 0);
    lstm_rec_kernel<<<NCTA, 256, REC_SMEM>>>(Whh0, 0);

    gemm_xw_kernel<<<ggrid, 256>>>(Wih1, bih1, bhh1, 1);
    lstm_rec_kernel<<<NCTA, 256, REC_SMEM>>>(Whh1, 1);

    out_kernel<<<(BB * HH + 255) / 256, 256>>>(sen_len, out);
}

// round 3
// speedup vs baseline: 1.6261x; 1.6261x over previous
#include <cuda_runtime.h>
#include <math.h>

#define TT   512
#define BB   64
#define HH   512
#define GG   2048   // 4*HH
#define EE   512
#define NCTA 128
#define UPC  4      // h-units per CTA  (HH / NCTA)
#define RPC  16     // gate rows per CTA (4 * UPC)

typedef unsigned long long u64;

// ---------------- packed fp32x2 helpers (sm_103a FFMA2) ----------------
__device__ __forceinline__ u64 pack2(float lo, float hi) {
    u64 r; asm("mov.b64 %0,{%1,%2};" : "=l"(r) : "f"(lo), "f"(hi)); return r;
}
__device__ __forceinline__ void ffma2(u64 &d, u64 a, u64 b) {
    asm("fma.rn.f32x2 %0,%1,%2,%0;" : "+l"(d) : "l"(a), "l"(b));
}
__device__ __forceinline__ float2 unpack2(u64 v) {
    float2 f; asm("mov.b64 {%0,%1},%2;" : "=f"(f.x), "=f"(f.y) : "l"(v)); return f;
}

// ---------------- scratch (device globals; no runtime allocation) ----------------
__device__ float g_x0[(size_t)TT * EE * BB];   // embedded input,  [T][E][B]
__device__ float g_xw[(size_t)TT * GG * BB];   // xW + bias,       [T][G][B]
__device__ float g_y0[(size_t)TT * HH * BB];   // layer0 outputs,  [T][H][B]
__device__ float g_y1[(size_t)TT * HH * BB];   // layer1 outputs,  [T][H][B]
__device__ float g_hbuf[2 * HH * BB];          // double-buffered h, [2][H][B]
__device__ unsigned g_bar;                     // grid barrier counter (monotonic)

// ---------------- grid barrier (128 co-resident CTAs, wrap-safe) ----------------
__device__ __forceinline__ void grid_sync() {
    __syncthreads();
    if (threadIdx.x == 0) {
        __threadfence();
        unsigned ticket = atomicAdd(&g_bar, 1u);
        unsigned target = ticket - (ticket & (NCTA - 1)) + NCTA;
        while ((int)(*(volatile unsigned*)&g_bar - target) < 0) { }
        __threadfence();
    }
    __syncthreads();
}

// ---------------- embedding gather ----------------
__global__ void embed_kernel(const int* __restrict__ src,
                             const float* __restrict__ emb) {
    size_t idx = (size_t)blockIdx.x * blockDim.x + threadIdx.x;
    if (idx >= (size_t)TT * EE * BB) return;
    int b = (int)(idx & 63);
    int e = (int)((idx >> 6) & (EE - 1));
    int t = (int)(idx >> 15);
    g_x0[idx] = emb[(size_t)src[t * BB + b] * EE + e];
}

// ---------------- GEMM: C[t][col][b] = sum_k A[t][k][b]*W[col][k] + bias ----------------
// Block: 64 batch x 128 cols, 128 threads, thread tile 8b x 8c, FFMA2 packed over batch.
__global__ void __launch_bounds__(128) gemm_xw_kernel(const float* __restrict__ W,
                                                      const float* __restrict__ b1,
                                                      const float* __restrict__ b2,
                                                      int layer) {
    const float* __restrict__ A = layer ? g_y0 : g_x0;
    float* __restrict__ C = g_xw;

    __shared__ float As[16][64];     // [k][b]
    __shared__ float Ws[16][132];    // [k][col], padded

    const int tid = threadIdx.x;
    const int t   = blockIdx.y;
    const int n0  = blockIdx.x * 128;
    const int bx  = tid & 7;            // batch group (8 batches)
    const int cy  = tid >> 3;           // col group (8 cols), 0..15
    const int b0  = bx * 8;
    const int c0  = cy * 8;
    const int lw_c = tid >> 2;          // 0..31 (W-load col within chunk)
    const int lw_q = tid & 3;           // 0..3  (W-load k quad)

    u64 acc[8][4];                      // [col][batch-pair]
    #pragma unroll
    for (int j = 0; j < 8; ++j)
        #pragma unroll
        for (int p = 0; p < 4; ++p) acc[j][p] = 0ull;

    for (int k0 = 0; k0 < 512; k0 += 16) {
        // A tile (already [k][b]): 2 float4 per thread
        #pragma unroll
        for (int u = 0; u < 2; ++u) {
            int f  = tid * 2 + u;
            int kk = f >> 4, bb4 = (f & 15) * 4;
            *(float4*)&As[kk][bb4] =
                *(const float4*)(A + ((size_t)t * 512 + k0 + kk) * 64 + bb4);
        }
        // W tile: transpose [col][k] -> [k][col]
        #pragma unroll
        for (int cb = 0; cb < 4; ++cb) {
            int c = cb * 32 + lw_c;
            float4 w = *(const float4*)(W + (size_t)(n0 + c) * 512 + k0 + lw_q * 4);
            Ws[lw_q * 4 + 0][c] = w.x;
            Ws[lw_q * 4 + 1][c] = w.y;
            Ws[lw_q * 4 + 2][c] = w.z;
            Ws[lw_q * 4 + 3][c] = w.w;
        }
        __syncthreads();

        #pragma unroll
        for (int kk = 0; kk < 16; ++kk) {
            ulonglong2 a01 = *(const ulonglong2*)&As[kk][b0];      // b0..b0+3
            ulonglong2 a23 = *(const ulonglong2*)&As[kk][b0 + 4];  // b0+4..b0+7
            float4 wA = *(const float4*)&Ws[kk][c0];
            float4 wB = *(const float4*)&Ws[kk][c0 + 4];
            float wv[8] = {wA.x, wA.y, wA.z, wA.w, wB.x, wB.y, wB.z, wB.w};
            #pragma unroll
            for (int j = 0; j < 8; ++j) {
                u64 wp = pack2(wv[j], wv[j]);
                ffma2(acc[j][0], a01.x, wp);
                ffma2(acc[j][1], a01.y, wp);
                ffma2(acc[j][2], a23.x, wp);
                ffma2(acc[j][3], a23.y, wp);
            }
        }
        __syncthreads();
    }

    #pragma unroll
    for (int j = 0; j < 8; ++j) {
        int col = n0 + c0 + j;
        float bias = b1[col] + b2[col];
        float2 p0 = unpack2(acc[j][0]);
        float2 p1 = unpack2(acc[j][1]);
        float2 p2 = unpack2(acc[j][2]);
        float2 p3 = unpack2(acc[j][3]);
        float4 v0 = make_float4(p0.x + bias, p0.y + bias, p1.x + bias, p1.y + bias);
        float4 v1 = make_float4(p2.x + bias, p2.y + bias, p3.x + bias, p3.y + bias);
        float* cp = C + ((size_t)t * GG + col) * BB + b0;
        *(float4*)cp       = v0;
        *(float4*)(cp + 4) = v1;
    }
}

// ---------------- persistent LSTM recurrence ----------------
// 128 CTAs x 256 threads. CTA owns 16 gate rows (4 h-units).
// Thread = (ks, rg, bg): 4-way k-split x 4 row-groups x 16 batch-groups.
// Thread tile: 4 rows x 4 batches over 128 k. Partials reduced via smem.
__global__ void __launch_bounds__(256, 1) lstm_rec_kernel(const float* __restrict__ Whh,
                                                          int layer) {
    extern __shared__ float smem[];
    float* sW = smem;                  // RPC*HH        = 8192  (32 KB)
    float* sH = sW + RPC * HH;         // HH*BB         = 32768 (128 KB)
    float* sP = sH + HH * BB;          // 4*RPC*BB      = 4096  (16 KB)
    float* sC = sP + 4 * RPC * BB;     // UPC*BB        = 256   (1 KB)

    const float* __restrict__ xw = g_xw;
    float* __restrict__ y = layer ? g_y1 : g_y0;
    float* hbuf = g_hbuf;

    const int tid = threadIdx.x;
    const int cta = blockIdx.x;
    const int u0  = cta * UPC;

    // Load Whh slice: local row r=q*4+j <-> global row q*HH+u0+j
    {
        const int r = tid >> 4;                 // 16 rows, 16 threads each
        const int q = r >> 2, j = r & 3;
        const float* srcw = Whh + (size_t)(q * HH + u0 + j) * HH;
        float* dstw = sW + r * HH;
        #pragma unroll
        for (int c = 0; c < 8; ++c) {
            int k = c * 64 + (tid & 15) * 4;
            *(float4*)(dstw + k) = *(const float4*)(srcw + k);
        }
    }
    for (int i = tid; i < UPC * BB; i += 256) sC[i] = 0.f;
    for (int i = tid; i < UPC * BB; i += 256) hbuf[u0 * BB + i] = 0.f;
    grid_sync();

    // dot-phase mapping
    const int bg = tid & 15;
    const int rg = (tid >> 4) & 3;
    const int ks = tid >> 6;
    const int b0 = bg * 4;
    const int r0 = rg * 4;
    const int kbase = ks * 128;
    const float* w0p = sW + (r0 + 0) * HH + kbase;
    const float* w1p = sW + (r0 + 1) * HH + kbase;
    const float* w2p = sW + (r0 + 2) * HH + kbase;
    const float* w3p = sW + (r0 + 3) * HH + kbase;
    // gate-phase mapping
    const int bb = tid & 63, jj = tid >> 6;

    int cur = 0;
    for (int t = 0; t < TT; ++t) {
        // stage h[cur] into smem (bypass L1: other CTAs wrote it)
        {
            const float4* hs = (const float4*)(hbuf + cur * HH * BB);
            float4* sh4 = (float4*)sH;
            #pragma unroll 8
            for (int i = tid; i < HH * BB / 4; i += 256) sh4[i] = __ldcg(hs + i);
        }
        __syncthreads();

        u64 acc0[4], acc1[4];
        #pragma unroll
        for (int i = 0; i < 4; ++i) { acc0[i] = 0ull; acc1[i] = 0ull; }

        const float* shk = sH + kbase * BB + b0;
        #pragma unroll 4
        for (int k4 = 0; k4 < 32; ++k4) {
            int k = k4 * 4;
            ulonglong2 h0 = *(const ulonglong2*)(shk + (k + 0) * BB);
            ulonglong2 h1 = *(const ulonglong2*)(shk + (k + 1) * BB);
            ulonglong2 h2 = *(const ulonglong2*)(shk + (k + 2) * BB);
            ulonglong2 h3 = *(const ulonglong2*)(shk + (k + 3) * BB);
            float4 w0 = *(const float4*)(w0p + k);
            float4 w1 = *(const float4*)(w1p + k);
            float4 w2 = *(const float4*)(w2p + k);
            float4 w3 = *(const float4*)(w3p + k);
            #define STEPKK(hh, c) { \
                u64 p0 = pack2(w0.c, w0.c), p1 = pack2(w1.c, w1.c); \
                u64 p2 = pack2(w2.c, w2.c), p3 = pack2(w3.c, w3.c); \
                ffma2(acc0[0], hh.x, p0); ffma2(acc1[0], hh.y, p0); \
                ffma2(acc0[1], hh.x, p1); ffma2(acc1[1], hh.y, p1); \
                ffma2(acc0[2], hh.x, p2); ffma2(acc1[2], hh.y, p2); \
                ffma2(acc0[3], hh.x, p3); ffma2(acc1[3], hh.y, p3); \
            }
            STEPKK(h0, x) STEPKK(h1, y) STEPKK(h2, z) STEPKK(h3, w)
            #undef STEPKK
        }
        #pragma unroll
        for (int i = 0; i < 4; ++i) {
            *(ulonglong2*)(sP + ((ks * RPC + r0 + i) * BB + b0)) =
                make_ulonglong2(acc0[i], acc1[i]);
        }
        __syncthreads();

        // gates: thread = (jj unit, bb batch)
        {
            float gv4[4];
            #pragma unroll
            for (int q = 0; q < 4; ++q) {
                int col = q * HH + u0 + jj;
                int r   = q * 4 + jj;
                float v = xw[((size_t)t * GG + col) * BB + bb];
                v += sP[(0 * RPC + r) * BB + bb];
                v += sP[(1 * RPC + r) * BB + bb];
                v += sP[(2 * RPC + r) * BB + bb];
                v += sP[(3 * RPC + r) * BB + bb];
                gv4[q] = v;
            }
            float iv = 1.f / (1.f + __expf(-gv4[0]));
            float fv = 1.f / (1.f + __expf(-gv4[1]));
            float gv = tanhf(gv4[2]);
            float ov = 1.f / (1.f + __expf(-gv4[3]));
            float c = fv * sC[jj * BB + bb] + iv * gv;
            sC[jj * BB + bb] = c;
            float h = ov * tanhf(c);
            hbuf[(cur ^ 1) * HH * BB + (u0 + jj) * BB + bb] = h;
            y[((size_t)t * HH + (u0 + jj)) * BB + bb] = h;
        }
        grid_sync();
        cur ^= 1;
    }
}

// ---------------- output gather ----------------
__global__ void out_kernel(const int* __restrict__ sen_len, float* __restrict__ out) {
    int idx = blockIdx.x * blockDim.x + threadIdx.x;
    if (idx >= BB * HH) return;
    int b = idx >> 9;
    int u = idx & (HH - 1);
    int t = sen_len[b] - 1;
    out[idx] = g_y1[((size_t)t * HH + u) * BB + b];
}

// ---------------- launch ----------------
static const int REC_SMEM = (RPC * HH + HH * BB + 4 * RPC * BB + UPC * BB) * (int)sizeof(float); // 181248

extern "C" void kernel_launch(void* const* d_in, const int* in_sizes, int n_in,
                              void* d_out, int out_size) {
    const int*   src     = (const int*)d_in[0];
    const int*   sen_len = (const int*)d_in[1];
    const float* emb     = (const float*)d_in[2];
    const float* Wih0    = (const float*)d_in[3];
    const float* Whh0    = (const float*)d_in[4];
    const float* bih0    = (const float*)d_in[5];
    const float* bhh0    = (const float*)d_in[6];
    const float* Wih1    = (const float*)d_in[7];
    const float* Whh1    = (const float*)d_in[8];
    const float* bih1    = (const float*)d_in[9];
    const float* bhh1    = (const float*)d_in[10];
    float* out = (float*)d_out;

    cudaFuncSetAttribute(lstm_rec_kernel,
                         cudaFuncAttributeMaxDynamicSharedMemorySize, REC_SMEM);

    embed_kernel<<<(TT * EE * BB + 255) / 256, 256>>>(src, emb);

    dim3 ggrid(GG / 128, TT);
    gemm_xw_kernel<<<ggrid, 128>>>(Wih0, bih0, bhh0, 0);
    lstm_rec_kernel<<<NCTA, 256, REC_SMEM>>>(Whh0, 0);

    gemm_xw_kernel<<<ggrid, 128>>>(Wih1, bih1, bhh1, 1);
    lstm_rec_kernel<<<NCTA, 256, REC_SMEM>>>(Whh1, 1);

    out_kernel<<<(BB * HH + 255) / 256, 256>>>(sen_len, out);
}